// round 16
// baseline (speedup 1.0000x reference)
#include <cuda_runtime.h>
#include <cuda_bf16.h>
#include <cstdint>

#define D_FEAT 128
#define D4 (D_FEAT / 4)      // 32 float4 per row
#define EPS 1e-6f

// ============ fast path: nodes_per_graph == 512, 2-CTA cluster ==============
// Cluster = one (graph, 32-feature chunk); each CTA owns 256 rows.
// 256 threads/CTA, ~60 regs -> 4 CTAs/SM: 4 independently-phased CTAs per SM
// keep the DRAM read stream busy through other CTAs' epilogues.
#define CL_THREADS 256
#define CL_CHUNK4  8          // 8 float4 cols = 32 features = 128B rows
#define CL_RG      (CL_THREADS / CL_CHUNK4)   // 32 row groups
#define CL_ITERS   8          // 256 rows / 32
#define CL_NWARPS  (CL_THREADS / 32)          // 8

__global__ __launch_bounds__(CL_THREADS, 4) __cluster_dims__(2, 1, 1)
void graphnorm_cluster(const float4* __restrict__ x,
                       const int*    __restrict__ n_node,
                       const float4* __restrict__ mean_scale,
                       const float4* __restrict__ scale,
                       const float4* __restrict__ bias,
                       float4* __restrict__ out)
{
    const int bid   = blockIdx.x;
    const int pair  = bid >> 1;          // (graph, chunk) id
    const int rank  = bid & 1;           // half of the graph (0: rows 0-255)
    const int g     = pair >> 2;
    const int chunk = pair & 3;

    const int t     = threadIdx.x;
    const int c     = t & (CL_CHUNK4 - 1);
    const int rg    = t >> 3;            // 0..31
    const int lane  = t & 31;
    const int w     = t >> 5;            // 0..7
    const int col4  = chunk * CL_CHUNK4 + c;

    const size_t base = (size_t)g * 512 * D4 + (size_t)(rank * 256) * D4 + col4;
    const float4* xg = x   + base;
    float4*       og = out + base;

    // ---- load 8 rows into registers, accumulate sum / sumsq ----
    float4 v[CL_ITERS];
    float4 s  = make_float4(0.f, 0.f, 0.f, 0.f);
    float4 s2 = make_float4(0.f, 0.f, 0.f, 0.f);
    #pragma unroll
    for (int i = 0; i < CL_ITERS; i++)
        v[i] = xg[(size_t)(rg + i * CL_RG) * D4];
    #pragma unroll
    for (int i = 0; i < CL_ITERS; i++) {
        s.x += v[i].x; s.y += v[i].y; s.z += v[i].z; s.w += v[i].w;
        s2.x = fmaf(v[i].x, v[i].x, s2.x);
        s2.y = fmaf(v[i].y, v[i].y, s2.y);
        s2.z = fmaf(v[i].z, v[i].z, s2.z);
        s2.w = fmaf(v[i].w, v[i].w, s2.w);
    }

    // ---- intra-warp reduce (threads sharing a column: lanes c, c+8, c+16, c+24)
    #pragma unroll
    for (int m = 8; m <= 16; m <<= 1) {
        s.x  += __shfl_xor_sync(0xffffffffu, s.x,  m);
        s.y  += __shfl_xor_sync(0xffffffffu, s.y,  m);
        s.z  += __shfl_xor_sync(0xffffffffu, s.z,  m);
        s.w  += __shfl_xor_sync(0xffffffffu, s.w,  m);
        s2.x += __shfl_xor_sync(0xffffffffu, s2.x, m);
        s2.y += __shfl_xor_sync(0xffffffffu, s2.y, m);
        s2.z += __shfl_xor_sync(0xffffffffu, s2.z, m);
        s2.w += __shfl_xor_sync(0xffffffffu, s2.w, m);
    }

    // ---- publish 8 warp-partials into LOCAL smem ----
    // layout: [slot = w*8 + col] contiguous float4, s then s2 array.
    __shared__ float4 sh_s [CL_NWARPS * CL_CHUNK4];
    __shared__ float4 sh_s2[CL_NWARPS * CL_CHUNK4];
    if (lane < CL_CHUNK4) {
        sh_s [w * CL_CHUNK4 + lane] = s;
        sh_s2[w * CL_CHUNK4 + lane] = s2;
    }

    // ---- cluster sync: both CTAs' partials visible cluster-wide ----
    asm volatile("barrier.cluster.arrive.aligned;" ::: "memory");
    asm volatile("barrier.cluster.wait.aligned;"   ::: "memory");

    // ---- stage 2: each thread sums 2 local + 2 remote slots, then shfl ----
    const int k0 = lane >> 3;            // 0..3  (warp-slot group)
    const int cc = lane & 7;             // column

    float4 a, b2;
    {
        float4 p0 = sh_s [ k0      * CL_CHUNK4 + cc];
        float4 p1 = sh_s [(k0 + 4) * CL_CHUNK4 + cc];
        float4 q0 = sh_s2[ k0      * CL_CHUNK4 + cc];
        float4 q1 = sh_s2[(k0 + 4) * CL_CHUNK4 + cc];
        a.x  = p0.x + p1.x; a.y  = p0.y + p1.y; a.z  = p0.z + p1.z; a.w  = p0.w + p1.w;
        b2.x = q0.x + q1.x; b2.y = q0.y + q1.y; b2.z = q0.z + q1.z; b2.w = q0.w + q1.w;
    }

    // remote (peer CTA) partials via DSMEM
    {
        uint32_t loc_s, loc_s2;
        asm("{ .reg .u64 a; cvta.to.shared.u64 a, %1; cvt.u32.u64 %0, a; }"
            : "=r"(loc_s)  : "l"((const void*)sh_s));
        asm("{ .reg .u64 a; cvta.to.shared.u64 a, %1; cvt.u32.u64 %0, a; }"
            : "=r"(loc_s2) : "l"((const void*)sh_s2));
        const uint32_t peer = 1u - (uint32_t)rank;
        uint32_t rem_s, rem_s2;
        asm("mapa.shared::cluster.u32 %0, %1, %2;" : "=r"(rem_s)  : "r"(loc_s),  "r"(peer));
        asm("mapa.shared::cluster.u32 %0, %1, %2;" : "=r"(rem_s2) : "r"(loc_s2), "r"(peer));

        const uint32_t off0 = (uint32_t)(( k0      * CL_CHUNK4 + cc) * 16);
        const uint32_t off1 = (uint32_t)(((k0 + 4) * CL_CHUNK4 + cc) * 16);

        float4 p0, p1, q0, q1;
        asm volatile("ld.shared::cluster.v4.f32 {%0,%1,%2,%3}, [%4];"
                     : "=f"(p0.x), "=f"(p0.y), "=f"(p0.z), "=f"(p0.w) : "r"(rem_s  + off0));
        asm volatile("ld.shared::cluster.v4.f32 {%0,%1,%2,%3}, [%4];"
                     : "=f"(p1.x), "=f"(p1.y), "=f"(p1.z), "=f"(p1.w) : "r"(rem_s  + off1));
        asm volatile("ld.shared::cluster.v4.f32 {%0,%1,%2,%3}, [%4];"
                     : "=f"(q0.x), "=f"(q0.y), "=f"(q0.z), "=f"(q0.w) : "r"(rem_s2 + off0));
        asm volatile("ld.shared::cluster.v4.f32 {%0,%1,%2,%3}, [%4];"
                     : "=f"(q1.x), "=f"(q1.y), "=f"(q1.z), "=f"(q1.w) : "r"(rem_s2 + off1));

        a.x  += p0.x + p1.x; a.y  += p0.y + p1.y; a.z  += p0.z + p1.z; a.w  += p0.w + p1.w;
        b2.x += q0.x + q1.x; b2.y += q0.y + q1.y; b2.z += q0.z + q1.z; b2.w += q0.w + q1.w;
    }

    // combine the 4 k-groups (lane bits 3..4); every lane ends with its column total
    #pragma unroll
    for (int m = 8; m <= 16; m <<= 1) {
        a.x  += __shfl_xor_sync(0xffffffffu, a.x,  m);
        a.y  += __shfl_xor_sync(0xffffffffu, a.y,  m);
        a.z  += __shfl_xor_sync(0xffffffffu, a.z,  m);
        a.w  += __shfl_xor_sync(0xffffffffu, a.w,  m);
        b2.x += __shfl_xor_sync(0xffffffffu, b2.x, m);
        b2.y += __shfl_xor_sync(0xffffffffu, b2.y, m);
        b2.z += __shfl_xor_sync(0xffffffffu, b2.z, m);
        b2.w += __shfl_xor_sync(0xffffffffu, b2.w, m);
    }

    // ---- second cluster sync: peers are done reading our smem -> safe to exit later
    asm volatile("barrier.cluster.arrive.aligned;" ::: "memory");
    asm volatile("barrier.cluster.wait.aligned;"   ::: "memory");

    // ---- per-feature constants (parallel; L2-hot) ----
    const float inv_n = 1.0f / (float)__ldg(&n_node[g]);
    const float4 ms = __ldg(&mean_scale[col4]);
    const float4 sc = __ldg(&scale[col4]);
    const float4 bi = __ldg(&bias[col4]);

    float4 mul, add;
    {
        float mean, m, var;
        mean = a.x * inv_n; m = mean * ms.x;
        var  = b2.x * inv_n - 2.0f * m * mean + m * m;
        mul.x = rsqrtf(var + EPS) * sc.x; add.x = bi.x - m * mul.x;

        mean = a.y * inv_n; m = mean * ms.y;
        var  = b2.y * inv_n - 2.0f * m * mean + m * m;
        mul.y = rsqrtf(var + EPS) * sc.y; add.y = bi.y - m * mul.y;

        mean = a.z * inv_n; m = mean * ms.z;
        var  = b2.z * inv_n - 2.0f * m * mean + m * m;
        mul.z = rsqrtf(var + EPS) * sc.z; add.z = bi.z - m * mul.z;

        mean = a.w * inv_n; m = mean * ms.w;
        var  = b2.w * inv_n - 2.0f * m * mean + m * m;
        mul.w = rsqrtf(var + EPS) * sc.w; add.w = bi.w - m * mul.w;
    }

    // ---- write y straight from registers ----
    #pragma unroll
    for (int i = 0; i < CL_ITERS; i++) {
        float4 y;
        y.x = fmaf(v[i].x, mul.x, add.x);
        y.y = fmaf(v[i].y, mul.y, add.y);
        y.z = fmaf(v[i].z, mul.z, add.z);
        y.w = fmaf(v[i].w, mul.w, add.w);
        og[(size_t)(rg + i * CL_RG) * D4] = y;
    }
}

// ---------------- generic fallback (two-pass, any nodes_per_graph) ----------
#define GTHREADS 512
#define GROWGROUPS (GTHREADS / D4)

__global__ __launch_bounds__(GTHREADS, 2)
void graphnorm_generic(const float4* __restrict__ x,
                       const int*    __restrict__ n_node,
                       const float4* __restrict__ mean_scale,
                       const float4* __restrict__ scale,
                       const float4* __restrict__ bias,
                       float4* __restrict__ out,
                       int nodes_per_graph)
{
    const int g     = blockIdx.x;
    const int t     = threadIdx.x;
    const int lane4 = t & (D4 - 1);
    const int rg    = t >> 5;

    const float4* xg = x   + (size_t)g * nodes_per_graph * D4;
    float4*       og = out + (size_t)g * nodes_per_graph * D4;

    float4 s  = make_float4(0.f, 0.f, 0.f, 0.f);
    float4 s2 = make_float4(0.f, 0.f, 0.f, 0.f);
    for (int r = rg; r < nodes_per_graph; r += GROWGROUPS) {
        float4 v = xg[(size_t)r * D4 + lane4];
        s.x += v.x; s.y += v.y; s.z += v.z; s.w += v.w;
        s2.x = fmaf(v.x, v.x, s2.x);
        s2.y = fmaf(v.y, v.y, s2.y);
        s2.z = fmaf(v.z, v.z, s2.z);
        s2.w = fmaf(v.w, v.w, s2.w);
    }

    __shared__ float4 sh_s [GROWGROUPS][D4];
    __shared__ float4 sh_s2[GROWGROUPS][D4];
    sh_s [rg][lane4] = s;
    sh_s2[rg][lane4] = s2;
    __syncthreads();

    #pragma unroll
    for (int step = GROWGROUPS / 2; step >= 1; step >>= 1) {
        if (rg < step) {
            float4 a = sh_s[rg][lane4],  b = sh_s[rg + step][lane4];
            a.x += b.x; a.y += b.y; a.z += b.z; a.w += b.w;
            sh_s[rg][lane4] = a;
            float4 cc = sh_s2[rg][lane4], d = sh_s2[rg + step][lane4];
            cc.x += d.x; cc.y += d.y; cc.z += d.z; cc.w += d.w;
            sh_s2[rg][lane4] = cc;
        }
        __syncthreads();
    }

    const float inv_n = 1.0f / (float)n_node[g];
    float4 tot  = sh_s [0][lane4];
    float4 tot2 = sh_s2[0][lane4];
    float4 ms = __ldg(&mean_scale[lane4]);
    float4 sc = __ldg(&scale[lane4]);
    float4 bi = __ldg(&bias[lane4]);

    float4 mul, add;
    {
        float mean, m, var;
        mean = tot.x * inv_n; m = mean * ms.x;
        var  = tot2.x * inv_n - 2.0f * m * mean + m * m;
        mul.x = rsqrtf(var + EPS) * sc.x; add.x = bi.x - m * mul.x;

        mean = tot.y * inv_n; m = mean * ms.y;
        var  = tot2.y * inv_n - 2.0f * m * mean + m * m;
        mul.y = rsqrtf(var + EPS) * sc.y; add.y = bi.y - m * mul.y;

        mean = tot.z * inv_n; m = mean * ms.z;
        var  = tot2.z * inv_n - 2.0f * m * mean + m * m;
        mul.z = rsqrtf(var + EPS) * sc.z; add.z = bi.z - m * mul.z;

        mean = tot.w * inv_n; m = mean * ms.w;
        var  = tot2.w * inv_n - 2.0f * m * mean + m * m;
        mul.w = rsqrtf(var + EPS) * sc.w; add.w = bi.w - m * mul.w;
    }

    for (int r = rg; r < nodes_per_graph; r += GROWGROUPS) {
        float4 v = xg[(size_t)r * D4 + lane4];
        float4 y;
        y.x = fmaf(v.x, mul.x, add.x);
        y.y = fmaf(v.y, mul.y, add.y);
        y.z = fmaf(v.z, mul.z, add.z);
        y.w = fmaf(v.w, mul.w, add.w);
        og[(size_t)r * D4 + lane4] = y;
    }
}

extern "C" void kernel_launch(void* const* d_in, const int* in_sizes, int n_in,
                              void* d_out, int out_size)
{
    const float* x          = (const float*)d_in[0];
    const int*   n_node     = (const int*)d_in[1];
    const float* mean_scale = (const float*)d_in[2];
    const float* scale      = (const float*)d_in[3];
    const float* bias       = (const float*)d_in[4];
    float*       out        = (float*)d_out;

    const int n_graph = in_sizes[1];
    const int total_nodes = in_sizes[0] / D_FEAT;
    const int nodes_per_graph = total_nodes / n_graph;

    if (nodes_per_graph == 512) {
        // grid = graphs * 4 chunks * 2 cluster halves
        graphnorm_cluster<<<n_graph * 8, CL_THREADS>>>(
            (const float4*)x, n_node,
            (const float4*)mean_scale, (const float4*)scale, (const float4*)bias,
            (float4*)out);
    } else {
        graphnorm_generic<<<n_graph, GTHREADS>>>(
            (const float4*)x, n_node,
            (const float4*)mean_scale, (const float4*)scale, (const float4*)bias,
            (float4*)out, nodes_per_graph);
    }
}